// round 7
// baseline (speedup 1.0000x reference)
#include <cuda_runtime.h>

// PositionEmbeddingEncoder — wavefront-minimized mapping (R4).
// lane t: point = pair*2 + (t>>4), depth = ((t>>1)&7)+1, half = t&1.
// Gather: lanes 2k,2k+1 read the two 16B halves of the SAME 32B table row.
// Depth-8 (w8, 512MB single-use) gathers use evict-first (__ldcs) so they
// don't thrash L2 lines holding the reusable w6/w7 tables.
// Store: (lane&15)*16B within the 256B point row -> 4 lines per STG.128.

#define HALF_SIZE  128.0f
#define U          8              // point-pairs per warp (unrolled)

__global__ __launch_bounds__(256)
void pee_kernel(const float* __restrict__ x,
                const float* __restrict__ w1,
                const float* __restrict__ w2,
                const float* __restrict__ w3,
                const float* __restrict__ w4,
                const float* __restrict__ w5,
                const float* __restrict__ w6,
                const float* __restrict__ w7,
                const float* __restrict__ w8,
                float* __restrict__ out,
                int n)
{
    const int lane   = threadIdx.x & 31;
    const int warpid = (blockIdx.x * (blockDim.x >> 5)) + (threadIdx.x >> 5);

    const int dm = (lane >> 1) & 7;       // 0..7  -> depth = dm+1
    const int h  = lane & 1;              // row half
    const int ps = lane >> 4;             // 0/1: which point of the pair

    const float* wp;
    switch (dm) {
        case 0: wp = w1; break;
        case 1: wp = w2; break;
        case 2: wp = w3; break;
        case 3: wp = w4; break;
        case 4: wp = w5; break;
        case 5: wp = w6; break;
        case 6: wp = w7; break;
        default: wp = w8; break;
    }

    const int   depth = dm + 1;
    const int   g     = 1 << depth;
    // (x+128) * (g/256): both scalings are exact powers of two, so this is
    // bit-identical to ((x+128)/256)*g as computed by the reference.
    const float kf    = (float)g * (1.0f / 256.0f);
    const bool  deep  = (dm == 7);

    const long long pair0 = (long long)warpid * U;

    float4 v[U];
    int    p[U];

#pragma unroll
    for (int u = 0; u < U; u++) {
        int pt = (int)((pair0 + u) * 2) + ps;
        p[u] = pt;
        if (pt < n) {
            float fx = (x[3 * pt + 0] + HALF_SIZE) * kf;
            float fy = (x[3 * pt + 1] + HALF_SIZE) * kf;
            float fz = (x[3 * pt + 2] + HALF_SIZE) * kf;

            int gx = min(max(__float2int_rd(fx), 0), g - 1);
            int gy = min(max(__float2int_rd(fy), 0), g - 1);
            int gz = min(max(__float2int_rd(fz), 0), g - 1);

            unsigned int flat = (unsigned int)gx
                              + ((unsigned int)gy << depth)
                              + ((unsigned int)gz << (2 * depth));

            const float4* addr = (const float4*)(wp + (size_t)flat * 8 + h * 4);
            if (deep)
                v[u] = __ldcs(addr);   // evict-first: single-use w8 lines
            else
                v[u] = __ldg(addr);    // normal: reusable small/mid tables
        }
    }

#pragma unroll
    for (int u = 0; u < U; u++) {
        if (p[u] < n) {
            __stcs((float4*)(out + (size_t)p[u] * 64) + (lane & 15), v[u]);
        }
    }
}

extern "C" void kernel_launch(void* const* d_in, const int* in_sizes, int n_in,
                              void* d_out, int out_size)
{
    const float* x  = (const float*)d_in[0];
    const float* w1 = (const float*)d_in[1];
    const float* w2 = (const float*)d_in[2];
    const float* w3 = (const float*)d_in[3];
    const float* w4 = (const float*)d_in[4];
    const float* w5 = (const float*)d_in[5];
    const float* w6 = (const float*)d_in[6];
    const float* w7 = (const float*)d_in[7];
    const float* w8 = (const float*)d_in[8];
    float* out = (float*)d_out;

    int n = in_sizes[0] / 3;

    // one warp covers U pairs = 2*U points; 8 warps per block
    int pts_per_block = 8 * U * 2;                   // 128
    int blocks = (n + pts_per_block - 1) / pts_per_block;
    pee_kernel<<<blocks, 256>>>(x, w1, w2, w3, w4, w5, w6, w7, w8, out, n);
}

// round 8
// speedup vs baseline: 1.2014x; 1.2014x over previous
#include <cuda_runtime.h>

// PositionEmbeddingEncoder — wavefront-minimized mapping (R5).
// lane t: point = pair*2 + (t>>4), depth = ((t>>1)&7)+1, half = t&1.
// Gather: lanes 2k,2k+1 read the two 16B halves of the SAME 32B table row
//   -> 16 distinct 128B lines per LDG.128 (vs 32 for point-per-thread).
// Store: (lane&15)*16B within the 256B point row -> 4 lines per STG.128.
// U=4 keeps regs <= 32 so 8 blocks/SM (64 warps) — occupancy is the
// latency-hiding mechanism here (R4 post-mortem: U=8 -> 56 regs -> 2x slower).
// Depth-8 lanes use __ldcs so w8's single-use random lines don't evict the
// reusable w6/w7 L2 footprint.

#define HALF_SIZE  128.0f
#define U          4              // point-pairs per warp (unrolled)

__global__ __launch_bounds__(256, 8)
void pee_kernel(const float* __restrict__ x,
                const float* __restrict__ w1,
                const float* __restrict__ w2,
                const float* __restrict__ w3,
                const float* __restrict__ w4,
                const float* __restrict__ w5,
                const float* __restrict__ w6,
                const float* __restrict__ w7,
                const float* __restrict__ w8,
                float* __restrict__ out,
                int n)
{
    const int lane   = threadIdx.x & 31;
    const int warpid = (blockIdx.x * (blockDim.x >> 5)) + (threadIdx.x >> 5);

    const int dm = (lane >> 1) & 7;       // 0..7  -> depth = dm+1
    const int h  = lane & 1;              // row half
    const int ps = lane >> 4;             // 0/1: which point of the pair

    const float* wp;
    switch (dm) {
        case 0: wp = w1; break;
        case 1: wp = w2; break;
        case 2: wp = w3; break;
        case 3: wp = w4; break;
        case 4: wp = w5; break;
        case 5: wp = w6; break;
        case 6: wp = w7; break;
        default: wp = w8; break;
    }

    const int   depth = dm + 1;
    const int   g     = 1 << depth;
    // (x+128) * (g/256): both scalings are exact powers of two, so this is
    // bit-identical to ((x+128)/256)*g as computed by the reference.
    const float kf    = (float)g * (1.0f / 256.0f);
    const bool  deep  = (dm == 7);

    const int pt0 = warpid * (U * 2) + ps;

    float4 v[U];
    int    p[U];

#pragma unroll
    for (int u = 0; u < U; u++) {
        int pt = pt0 + u * 2;
        p[u] = pt;
        if (pt < n) {
            float fx = (x[3 * pt + 0] + HALF_SIZE) * kf;
            float fy = (x[3 * pt + 1] + HALF_SIZE) * kf;
            float fz = (x[3 * pt + 2] + HALF_SIZE) * kf;

            int gx = min(max(__float2int_rd(fx), 0), g - 1);
            int gy = min(max(__float2int_rd(fy), 0), g - 1);
            int gz = min(max(__float2int_rd(fz), 0), g - 1);

            unsigned int flat = (unsigned int)gx
                              + ((unsigned int)gy << depth)
                              + ((unsigned int)gz << (2 * depth));

            const float4* addr = (const float4*)(wp + (size_t)flat * 8 + h * 4);
            if (deep)
                v[u] = __ldcs(addr);   // evict-first: single-use w8 lines
            else
                v[u] = __ldg(addr);    // normal: reusable small/mid tables
        }
    }

#pragma unroll
    for (int u = 0; u < U; u++) {
        if (p[u] < n) {
            __stcs((float4*)(out + (size_t)p[u] * 64) + (lane & 15), v[u]);
        }
    }
}

extern "C" void kernel_launch(void* const* d_in, const int* in_sizes, int n_in,
                              void* d_out, int out_size)
{
    const float* x  = (const float*)d_in[0];
    const float* w1 = (const float*)d_in[1];
    const float* w2 = (const float*)d_in[2];
    const float* w3 = (const float*)d_in[3];
    const float* w4 = (const float*)d_in[4];
    const float* w5 = (const float*)d_in[5];
    const float* w6 = (const float*)d_in[6];
    const float* w7 = (const float*)d_in[7];
    const float* w8 = (const float*)d_in[8];
    float* out = (float*)d_out;

    int n = in_sizes[0] / 3;

    // one warp covers U pairs = 2*U points; 8 warps per block
    int pts_per_block = 8 * U * 2;                   // 64
    int blocks = (n + pts_per_block - 1) / pts_per_block;
    pee_kernel<<<blocks, 256>>>(x, w1, w2, w3, w4, w5, w6, w7, w8, out, n);
}